// round 1
// baseline (speedup 1.0000x reference)
#include <cuda_runtime.h>
#include <cuda_bf16.h>
#include <math.h>

// ---------------------------------------------------------------------------
// Problem constants
// ---------------------------------------------------------------------------
#define NB 4            // batch
#define NN 15135        // nodes
#define NE 302700       // edges (without self loops)
#define FIN0 8          // layer0 input features
#define NH 64           // hidden
#define NFC 256
#define NEG_SLOPE 0.2f

// ---------------------------------------------------------------------------
// Static device scratch (no allocations allowed)
// ---------------------------------------------------------------------------
__device__ int   g_deg[NN];
__device__ int   g_cur[NN];
__device__ int   g_rowptr[NN + 1];
__device__ int   g_col[NE];

__device__ float g_hin[NB * NN * NH];        // transformed features (current layer)
__device__ float g_hout[3][NB * NN * NH];    // per-layer GAT outputs (needed for fc)
__device__ float g_es[NB * NN];
__device__ float g_ed[NB * NN];
__device__ float g_scores[NB * NN];
__device__ float g_h1[NB * NFC];

__device__ __forceinline__ float lrelu(float x) {
    return x >= 0.f ? x : NEG_SLOPE * x;
}

// ---------------------------------------------------------------------------
// CSR construction
// ---------------------------------------------------------------------------
__global__ void zero_kernel() {
    int i = blockIdx.x * blockDim.x + threadIdx.x;
    if (i < NN) g_deg[i] = 0;
    if (i < NB * NFC) g_h1[i] = 0.f;
}

__global__ void hist_kernel(const int* __restrict__ ei) {
    int e = blockIdx.x * blockDim.x + threadIdx.x;
    if (e < NE) atomicAdd(&g_deg[ei[NE + e]], 1);   // row 1 = dst
}

__global__ void scan_kernel() {
    __shared__ int sdata[1024];
    __shared__ int carry;
    int t = threadIdx.x;
    if (t == 0) { carry = 0; g_rowptr[0] = 0; }
    __syncthreads();
    for (int base = 0; base < NN; base += 1024) {
        int idx = base + t;
        int v = (idx < NN) ? g_deg[idx] : 0;
        sdata[t] = v;
        __syncthreads();
        // Hillis-Steele inclusive scan
        for (int off = 1; off < 1024; off <<= 1) {
            int x = (t >= off) ? sdata[t - off] : 0;
            __syncthreads();
            sdata[t] += x;
            __syncthreads();
        }
        if (idx < NN) g_rowptr[idx + 1] = sdata[t] + carry;
        __syncthreads();
        if (t == 0) carry += sdata[1023];
        __syncthreads();
    }
}

__global__ void copycur_kernel() {
    int i = blockIdx.x * blockDim.x + threadIdx.x;
    if (i < NN) g_cur[i] = g_rowptr[i];
}

__global__ void scatter_kernel(const int* __restrict__ ei) {
    int e = blockIdx.x * blockDim.x + threadIdx.x;
    if (e < NE) {
        int s = ei[e];
        int d = ei[NE + e];
        int pos = atomicAdd(&g_cur[d], 1);
        g_col[pos] = s;
    }
}

// ---------------------------------------------------------------------------
// Feature transform: h = in @ W ; es = h.a_src ; ed = h.a_dst
// One warp per (b,n) row. W staged in shared.
// ---------------------------------------------------------------------------
template <int FIN>
__global__ void transform_kernel(const float* __restrict__ x0,
                                 const float* __restrict__ W,
                                 const float* __restrict__ a_src,
                                 const float* __restrict__ a_dst,
                                 int layer) {
    __shared__ float Ws[FIN * NH];
    int t = threadIdx.x;
    for (int i = t; i < FIN * NH; i += blockDim.x) Ws[i] = W[i];
    __syncthreads();

    int warp = (blockIdx.x * blockDim.x + t) >> 5;
    int lane = t & 31;
    if (warp >= NB * NN) return;

    const float* in = (layer == 0) ? x0 : g_hout[layer - 1];
    const float* row = in + (size_t)warp * FIN;

    float acc0 = 0.f, acc1 = 0.f;
#pragma unroll
    for (int f = 0; f < FIN; ++f) {
        float xv = row[f];
        acc0 = fmaf(xv, Ws[f * NH + lane], acc0);
        acc1 = fmaf(xv, Ws[f * NH + lane + 32], acc1);
    }
    float* hrow = g_hin + (size_t)warp * NH;
    hrow[lane] = acc0;
    hrow[lane + 32] = acc1;

    float e_s = acc0 * a_src[lane] + acc1 * a_src[lane + 32];
    float e_d = acc0 * a_dst[lane] + acc1 * a_dst[lane + 32];
#pragma unroll
    for (int o = 16; o; o >>= 1) {
        e_s += __shfl_xor_sync(0xffffffffu, e_s, o);
        e_d += __shfl_xor_sync(0xffffffffu, e_d, o);
    }
    if (lane == 0) {
        g_es[warp] = e_s;
        g_ed[warp] = e_d;
    }
}

// ---------------------------------------------------------------------------
// GAT aggregation: one warp per dst node v, all 4 batches together.
// Pass1: segment max; Pass2: exp-sum; Pass3: weighted gather of h[src].
// Self-loop folded in analytically.
// ---------------------------------------------------------------------------
__global__ void agg_kernel(const float* __restrict__ bias, int layer) {
    int warp = (blockIdx.x * blockDim.x + threadIdx.x) >> 5;
    int lane = threadIdx.x & 31;
    if (warp >= NN) return;
    int v = warp;
    int r0 = g_rowptr[v];
    int r1 = g_rowptr[v + 1];

    float edv[NB], ess[NB];
#pragma unroll
    for (int b = 0; b < NB; ++b) {
        edv[b] = g_ed[b * NN + v];
        ess[b] = g_es[b * NN + v];
    }

    // pass 1: max (self loop seeded on lane 0)
    float mx[NB];
#pragma unroll
    for (int b = 0; b < NB; ++b)
        mx[b] = (lane == 0) ? lrelu(ess[b] + edv[b]) : -1e30f;
    for (int i = r0 + lane; i < r1; i += 32) {
        int s = g_col[i];
#pragma unroll
        for (int b = 0; b < NB; ++b)
            mx[b] = fmaxf(mx[b], lrelu(g_es[b * NN + s] + edv[b]));
    }
#pragma unroll
    for (int o = 16; o; o >>= 1) {
#pragma unroll
        for (int b = 0; b < NB; ++b)
            mx[b] = fmaxf(mx[b], __shfl_xor_sync(0xffffffffu, mx[b], o));
    }

    // pass 2: sum of exp
    float sm[NB];
#pragma unroll
    for (int b = 0; b < NB; ++b)
        sm[b] = (lane == 0) ? __expf(lrelu(ess[b] + edv[b]) - mx[b]) : 0.f;
    for (int i = r0 + lane; i < r1; i += 32) {
        int s = g_col[i];
#pragma unroll
        for (int b = 0; b < NB; ++b)
            sm[b] += __expf(lrelu(g_es[b * NN + s] + edv[b]) - mx[b]);
    }
#pragma unroll
    for (int o = 16; o; o >>= 1) {
#pragma unroll
        for (int b = 0; b < NB; ++b)
            sm[b] += __shfl_xor_sync(0xffffffffu, sm[b], o);
    }
    float inv[NB];
#pragma unroll
    for (int b = 0; b < NB; ++b) inv[b] = 1.f / sm[b];

    // pass 3: weighted gather. Each lane owns features 2*lane, 2*lane+1.
    float acc[2 * NB];
#pragma unroll
    for (int i = 0; i < 2 * NB; ++i) acc[i] = 0.f;

    for (int i = r0; i < r1; ++i) {
        int s = g_col[i];   // broadcast across warp
#pragma unroll
        for (int b = 0; b < NB; ++b) {
            float w = __expf(lrelu(g_es[b * NN + s] + edv[b]) - mx[b]) * inv[b];
            float2 hv = *(const float2*)(g_hin + ((size_t)(b * NN + s)) * NH + 2 * lane);
            acc[2 * b]     = fmaf(w, hv.x, acc[2 * b]);
            acc[2 * b + 1] = fmaf(w, hv.y, acc[2 * b + 1]);
        }
    }
    // self loop contribution
#pragma unroll
    for (int b = 0; b < NB; ++b) {
        float w = __expf(lrelu(ess[b] + edv[b]) - mx[b]) * inv[b];
        float2 hv = *(const float2*)(g_hin + ((size_t)(b * NN + v)) * NH + 2 * lane);
        acc[2 * b]     = fmaf(w, hv.x, acc[2 * b]);
        acc[2 * b + 1] = fmaf(w, hv.y, acc[2 * b + 1]);
    }

    float bb0 = bias[2 * lane];
    float bb1 = bias[2 * lane + 1];
    float* out = g_hout[layer];
#pragma unroll
    for (int b = 0; b < NB; ++b) {
        float2 o;
        o.x = fmaxf(acc[2 * b] + bb0, 0.f);
        o.y = fmaxf(acc[2 * b + 1] + bb1, 0.f);
        *(float2*)(out + ((size_t)(b * NN + v)) * NH + 2 * lane) = o;
    }
}

// ---------------------------------------------------------------------------
// scores[b,n] = sum_{h,l} hout_l[b,n,h] * fc_w[h*3+l] + fc_b
// One warp per (b,n).
// ---------------------------------------------------------------------------
__global__ void scores_kernel(const float* __restrict__ fcw,
                              const float* __restrict__ fcb) {
    int warp = (blockIdx.x * blockDim.x + threadIdx.x) >> 5;
    int lane = threadIdx.x & 31;
    if (warp >= NB * NN) return;

    size_t off = (size_t)warp * NH;
    int j0 = lane, j1 = lane + 32;
    float acc = 0.f;
#pragma unroll
    for (int l = 0; l < 3; ++l) {
        acc = fmaf(g_hout[l][off + j0], fcw[j0 * 3 + l], acc);
        acc = fmaf(g_hout[l][off + j1], fcw[j1 * 3 + l], acc);
    }
#pragma unroll
    for (int o = 16; o; o >>= 1) acc += __shfl_xor_sync(0xffffffffu, acc, o);
    if (lane == 0) g_scores[warp] = acc + fcb[0];
}

// ---------------------------------------------------------------------------
// h1[b,f] = sum_n scores[b,n] * lin1_w[n,f]  (accumulated via atomics)
// ---------------------------------------------------------------------------
__global__ void lin1_kernel(const float* __restrict__ w) {
    int f = threadIdx.x;  // 0..255
    int chunk = (NN + gridDim.x - 1) / gridDim.x;
    int n0 = blockIdx.x * chunk;
    int n1 = n0 + chunk;
    if (n1 > NN) n1 = NN;

    float acc[NB] = {0.f, 0.f, 0.f, 0.f};
    for (int n = n0; n < n1; ++n) {
        float wv = w[(size_t)n * NFC + f];
#pragma unroll
        for (int b = 0; b < NB; ++b)
            acc[b] = fmaf(g_scores[b * NN + n], wv, acc[b]);
    }
#pragma unroll
    for (int b = 0; b < NB; ++b)
        atomicAdd(&g_h1[b * NFC + f], acc[b]);
}

// ---------------------------------------------------------------------------
// relu(h1 + lin1_b) -> logits -> log_softmax -> out[4,2]
// ---------------------------------------------------------------------------
__global__ void final_kernel(const float* __restrict__ l1b,
                             const float* __restrict__ l2w,
                             const float* __restrict__ l2b,
                             float* __restrict__ out) {
    __shared__ float s0[NFC], s1[NFC];
    int f = threadIdx.x;
    for (int b = 0; b < NB; ++b) {
        float hv = fmaxf(g_h1[b * NFC + f] + l1b[f], 0.f);
        s0[f] = hv * l2w[f * 2 + 0];
        s1[f] = hv * l2w[f * 2 + 1];
        __syncthreads();
        for (int off = 128; off; off >>= 1) {
            if (f < off) { s0[f] += s0[f + off]; s1[f] += s1[f + off]; }
            __syncthreads();
        }
        if (f == 0) {
            float l0 = s0[0] + l2b[0];
            float l1 = s1[0] + l2b[1];
            float m = fmaxf(l0, l1);
            float lse = m + logf(expf(l0 - m) + expf(l1 - m));
            out[b * 2 + 0] = l0 - lse;
            out[b * 2 + 1] = l1 - lse;
        }
        __syncthreads();
    }
}

// ---------------------------------------------------------------------------
// Launch
// ---------------------------------------------------------------------------
extern "C" void kernel_launch(void* const* d_in, const int* in_sizes, int n_in,
                              void* d_out, int out_size) {
    const float* x      = (const float*)d_in[0];
    const int*   ei     = (const int*)d_in[1];
    const float* W[3]   = {(const float*)d_in[3], (const float*)d_in[7],  (const float*)d_in[11]};
    const float* as_[3] = {(const float*)d_in[4], (const float*)d_in[8],  (const float*)d_in[12]};
    const float* ad_[3] = {(const float*)d_in[5], (const float*)d_in[9],  (const float*)d_in[13]};
    const float* bb[3]  = {(const float*)d_in[6], (const float*)d_in[10], (const float*)d_in[14]};
    const float* fcw    = (const float*)d_in[15];
    const float* fcb    = (const float*)d_in[16];
    const float* l1w    = (const float*)d_in[17];
    const float* l1b    = (const float*)d_in[18];
    const float* l2w    = (const float*)d_in[19];
    const float* l2b    = (const float*)d_in[20];
    float* out = (float*)d_out;

    // CSR build (re-done every replay; cheap, deterministic work)
    zero_kernel<<<(NN + 255) / 256, 256>>>();
    hist_kernel<<<(NE + 255) / 256, 256>>>(ei);
    scan_kernel<<<1, 1024>>>();
    copycur_kernel<<<(NN + 255) / 256, 256>>>();
    scatter_kernel<<<(NE + 255) / 256, 256>>>(ei);

    int gridT = (NB * NN + 7) / 8;   // one warp per (b,n), 8 warps/block
    int gridA = (NN + 7) / 8;        // one warp per node

    // layer 0
    transform_kernel<FIN0><<<gridT, 256>>>(x, W[0], as_[0], ad_[0], 0);
    agg_kernel<<<gridA, 256>>>(bb[0], 0);
    // layer 1
    transform_kernel<NH><<<gridT, 256>>>(x, W[1], as_[1], ad_[1], 1);
    agg_kernel<<<gridA, 256>>>(bb[1], 1);
    // layer 2
    transform_kernel<NH><<<gridT, 256>>>(x, W[2], as_[2], ad_[2], 2);
    agg_kernel<<<gridA, 256>>>(bb[2], 2);

    scores_kernel<<<gridT, 256>>>(fcw, fcb);
    lin1_kernel<<<64, 256>>>(l1w);
    final_kernel<<<1, 256>>>(l1b, l2w, l2b, out);
}

// round 2
// speedup vs baseline: 1.2295x; 1.2295x over previous
#include <cuda_runtime.h>
#include <cuda_bf16.h>
#include <math.h>

#define NB 4
#define NN 15135
#define NE 302700
#define FIN0 8
#define NH 64
#define NFC 256
#define NEG_SLOPE 0.2f

// ---------------------------------------------------------------------------
// Static device scratch
// ---------------------------------------------------------------------------
__device__ int    g_deg[NN];
__device__ int    g_cur[NN];
__device__ int    g_rowptr[NN + 1];
__device__ int    g_col[NE];

__device__ float  g_hin[(size_t)NN * 256];       // [n][b*64+f] interleaved
__device__ float  g_hout[3][NB * NN * NH];       // [l][b][n][64]
__device__ float4 g_es4[NN];                     // es for all 4 batches
__device__ float4 g_ed4[NN];
__device__ float4 g_w[NE];                       // unnormalized softmax numerators
__device__ float  g_scores[NB * NN];
__device__ float  g_h1[NB * NFC];

__device__ __forceinline__ float lrelu(float x) { return x >= 0.f ? x : NEG_SLOPE * x; }
__device__ __forceinline__ float4 lrelu4(float4 a) {
    return make_float4(lrelu(a.x), lrelu(a.y), lrelu(a.z), lrelu(a.w));
}
__device__ __forceinline__ float4 add4(float4 a, float4 b) {
    return make_float4(a.x + b.x, a.y + b.y, a.z + b.z, a.w + b.w);
}
__device__ __forceinline__ float4 max4(float4 a, float4 b) {
    return make_float4(fmaxf(a.x, b.x), fmaxf(a.y, b.y), fmaxf(a.z, b.z), fmaxf(a.w, b.w));
}
__device__ __forceinline__ float4 expsub4(float4 a, float4 m) {
    return make_float4(__expf(a.x - m.x), __expf(a.y - m.y), __expf(a.z - m.z), __expf(a.w - m.w));
}

// ---------------------------------------------------------------------------
// CSR construction
// ---------------------------------------------------------------------------
__global__ void zero_kernel() {
    int i = blockIdx.x * blockDim.x + threadIdx.x;
    if (i < NN) g_deg[i] = 0;
    if (i < NB * NFC) g_h1[i] = 0.f;
}

__global__ void hist_kernel(const int* __restrict__ ei) {
    int e = blockIdx.x * blockDim.x + threadIdx.x;
    if (e < NE) atomicAdd(&g_deg[ei[NE + e]], 1);
}

// shuffle-based single-block scan; also writes g_cur (= exclusive prefix)
__global__ void scan_kernel() {
    __shared__ int warpsums[32];
    __shared__ int carry;
    int t = threadIdx.x;
    int lane = t & 31, w = t >> 5;
    if (t == 0) { carry = 0; g_rowptr[0] = 0; }
    __syncthreads();
    for (int base = 0; base < NN; base += 1024) {
        int idx = base + t;
        int v = (idx < NN) ? g_deg[idx] : 0;
        int x = v;
#pragma unroll
        for (int off = 1; off < 32; off <<= 1) {
            int y = __shfl_up_sync(0xffffffffu, x, off);
            if (lane >= off) x += y;
        }
        if (lane == 31) warpsums[w] = x;
        __syncthreads();
        if (t < 32) {
            int s = warpsums[t];
#pragma unroll
            for (int off = 1; off < 32; off <<= 1) {
                int y = __shfl_up_sync(0xffffffffu, s, off);
                if (t >= off) s += y;
            }
            warpsums[t] = s;
        }
        __syncthreads();
        int incl = x + (w > 0 ? warpsums[w - 1] : 0) + carry;
        if (idx < NN) {
            g_rowptr[idx + 1] = incl;
            g_cur[idx] = incl - v;
        }
        __syncthreads();
        if (t == 1023) carry = incl;
        __syncthreads();
    }
}

__global__ void scatter_kernel(const int* __restrict__ ei) {
    int e = blockIdx.x * blockDim.x + threadIdx.x;
    if (e < NE) {
        int s = ei[e];
        int d = ei[NE + e];
        int pos = atomicAdd(&g_cur[d], 1);
        g_col[pos] = s;
    }
}

// ---------------------------------------------------------------------------
// Feature transform. One warp per (b,n).
// Writes g_hin interleaved [n][b*64+f] and es/ed into float4-per-node arrays.
// ---------------------------------------------------------------------------
template <int FIN>
__global__ void transform_kernel(const float* __restrict__ x0,
                                 const float* __restrict__ W,
                                 const float* __restrict__ a_src,
                                 const float* __restrict__ a_dst,
                                 int layer) {
    __shared__ float Ws[FIN * NH];
    int t = threadIdx.x;
    for (int i = t; i < FIN * NH; i += blockDim.x) Ws[i] = W[i];
    __syncthreads();

    int warp = (blockIdx.x * blockDim.x + t) >> 5;
    int lane = t & 31;
    if (warp >= NB * NN) return;
    int b = warp / NN;
    int n = warp - b * NN;

    const float* in = (layer == 0) ? x0 : g_hout[layer - 1];
    const float* row = in + (size_t)warp * FIN;

    float acc0 = 0.f, acc1 = 0.f;
#pragma unroll
    for (int f = 0; f < FIN; ++f) {
        float xv = row[f];
        acc0 = fmaf(xv, Ws[f * NH + lane], acc0);
        acc1 = fmaf(xv, Ws[f * NH + lane + 32], acc1);
    }
    float* hrow = g_hin + (size_t)n * 256 + b * 64;
    hrow[lane] = acc0;
    hrow[lane + 32] = acc1;

    float e_s = acc0 * a_src[lane] + acc1 * a_src[lane + 32];
    float e_d = acc0 * a_dst[lane] + acc1 * a_dst[lane + 32];
#pragma unroll
    for (int o = 16; o; o >>= 1) {
        e_s += __shfl_xor_sync(0xffffffffu, e_s, o);
        e_d += __shfl_xor_sync(0xffffffffu, e_d, o);
    }
    if (lane == 0) {
        ((float*)g_es4)[n * 4 + b] = e_s;
        ((float*)g_ed4)[n * 4 + b] = e_d;
    }
}

// ---------------------------------------------------------------------------
// GAT aggregation: one warp per dst node, all 4 batches.
// Fused max+expsum pass (logit cached in regs for deg<=32), then gather pass.
// Optionally fuses the per-node fc scores (layer 2).
// ---------------------------------------------------------------------------
template <bool FUSE_SCORES>
__global__ void agg_kernel(const float* __restrict__ bias, int layer,
                           const float* __restrict__ fcw,
                           const float* __restrict__ fcb) {
    int warp = (blockIdx.x * blockDim.x + threadIdx.x) >> 5;
    int lane = threadIdx.x & 31;
    if (warp >= NN) return;
    int v = warp;
    int r0 = g_rowptr[v];
    int r1 = g_rowptr[v + 1];

    float4 ed4 = g_ed4[v];
    float4 es4 = g_es4[v];
    float4 vself = lrelu4(add4(es4, ed4));

    // ---- pass 1: max (cache first edge's logit per lane) ----
    int i0 = r0 + lane;
    float4 v0 = make_float4(0.f, 0.f, 0.f, 0.f);
    bool have0 = (i0 < r1);
    if (have0) {
        int s = g_col[i0];
        v0 = lrelu4(add4(g_es4[s], ed4));
    }
    float4 mx = vself;                       // self loop participates in max
    if (have0) mx = max4(mx, v0);
    for (int i = i0 + 32; i < r1; i += 32) {
        int s = g_col[i];
        mx = max4(mx, lrelu4(add4(g_es4[s], ed4)));
    }
#pragma unroll
    for (int o = 16; o; o >>= 1) {
        mx.x = fmaxf(mx.x, __shfl_xor_sync(0xffffffffu, mx.x, o));
        mx.y = fmaxf(mx.y, __shfl_xor_sync(0xffffffffu, mx.y, o));
        mx.z = fmaxf(mx.z, __shfl_xor_sync(0xffffffffu, mx.z, o));
        mx.w = fmaxf(mx.w, __shfl_xor_sync(0xffffffffu, mx.w, o));
    }

    // ---- pass 2: exp, store numerators, sum ----
    float4 sm = make_float4(0.f, 0.f, 0.f, 0.f);
    float4 wself = expsub4(vself, mx);
    if (lane == 0) sm = wself;               // self counted once
    if (have0) {
        float4 ex = expsub4(v0, mx);
        g_w[i0] = ex;
        sm = add4(sm, ex);
    }
    for (int i = i0 + 32; i < r1; i += 32) {
        int s = g_col[i];
        float4 ex = expsub4(lrelu4(add4(g_es4[s], ed4)), mx);
        g_w[i] = ex;
        sm = add4(sm, ex);
    }
#pragma unroll
    for (int o = 16; o; o >>= 1) {
        sm.x += __shfl_xor_sync(0xffffffffu, sm.x, o);
        sm.y += __shfl_xor_sync(0xffffffffu, sm.y, o);
        sm.z += __shfl_xor_sync(0xffffffffu, sm.z, o);
        sm.w += __shfl_xor_sync(0xffffffffu, sm.w, o);
    }
    float4 inv = make_float4(1.f / sm.x, 1.f / sm.y, 1.f / sm.z, 1.f / sm.w);

    // lane -> (batch, feature) mapping: lo covers batches 0/1, hi batches 2/3
    bool loA = (lane < 16);                  // lo-half batch: 0 if lane<16 else 1
    float invL = loA ? inv.x : inv.y;
    float invH = loA ? inv.z : inv.w;

    // ---- pass 3: weighted gather (one 1024B block per edge) ----
    float4 accL = make_float4(0.f, 0.f, 0.f, 0.f);
    float4 accH = make_float4(0.f, 0.f, 0.f, 0.f);
    for (int i = r0; i < r1; ++i) {
        int s = g_col[i];                    // warp-broadcast
        float4 w4 = g_w[i];                  // warp-broadcast
        float wl = (loA ? w4.x : w4.y) * invL;
        float wh = (loA ? w4.z : w4.w) * invH;
        const float* hp = g_hin + (size_t)s * 256 + lane * 4;
        float4 hl = *(const float4*)hp;
        float4 hh = *(const float4*)(hp + 128);
        accL.x = fmaf(wl, hl.x, accL.x); accL.y = fmaf(wl, hl.y, accL.y);
        accL.z = fmaf(wl, hl.z, accL.z); accL.w = fmaf(wl, hl.w, accL.w);
        accH.x = fmaf(wh, hh.x, accH.x); accH.y = fmaf(wh, hh.y, accH.y);
        accH.z = fmaf(wh, hh.z, accH.z); accH.w = fmaf(wh, hh.w, accH.w);
    }
    {   // self loop
        float wl = (loA ? wself.x : wself.y) * invL;
        float wh = (loA ? wself.z : wself.w) * invH;
        const float* hp = g_hin + (size_t)v * 256 + lane * 4;
        float4 hl = *(const float4*)hp;
        float4 hh = *(const float4*)(hp + 128);
        accL.x = fmaf(wl, hl.x, accL.x); accL.y = fmaf(wl, hl.y, accL.y);
        accL.z = fmaf(wl, hl.z, accL.z); accL.w = fmaf(wl, hl.w, accL.w);
        accH.x = fmaf(wh, hh.x, accH.x); accH.y = fmaf(wh, hh.y, accH.y);
        accH.z = fmaf(wh, hh.z, accH.z); accH.w = fmaf(wh, hh.w, accH.w);
    }

    int bL = lane >> 4;                      // 0 or 1
    int f0 = (lane & 15) * 4;
    float4 b4 = *(const float4*)(bias + f0);
    float4 oL, oH;
    oL.x = fmaxf(accL.x + b4.x, 0.f); oL.y = fmaxf(accL.y + b4.y, 0.f);
    oL.z = fmaxf(accL.z + b4.z, 0.f); oL.w = fmaxf(accL.w + b4.w, 0.f);
    oH.x = fmaxf(accH.x + b4.x, 0.f); oH.y = fmaxf(accH.y + b4.y, 0.f);
    oH.z = fmaxf(accH.z + b4.z, 0.f); oH.w = fmaxf(accH.w + b4.w, 0.f);

    float* out = g_hout[layer];
    *(float4*)(out + ((size_t)(bL * NN + v)) * NH + f0) = oL;
    *(float4*)(out + ((size_t)((bL + 2) * NN + v)) * NH + f0) = oH;

    if (FUSE_SCORES) {
        // scores[b,v] = sum_j sum_l hout_l[b,v,j] * fcw[j*3+l]  (+ fcb)
        float4 w2 = make_float4(fcw[(f0 + 0) * 3 + 2], fcw[(f0 + 1) * 3 + 2],
                                fcw[(f0 + 2) * 3 + 2], fcw[(f0 + 3) * 3 + 2]);
        float4 w0 = make_float4(fcw[(f0 + 0) * 3 + 0], fcw[(f0 + 1) * 3 + 0],
                                fcw[(f0 + 2) * 3 + 0], fcw[(f0 + 3) * 3 + 0]);
        float4 w1 = make_float4(fcw[(f0 + 0) * 3 + 1], fcw[(f0 + 1) * 3 + 1],
                                fcw[(f0 + 2) * 3 + 1], fcw[(f0 + 3) * 3 + 1]);
        float4 h0L = *(const float4*)(g_hout[0] + ((size_t)(bL * NN + v)) * NH + f0);
        float4 h0H = *(const float4*)(g_hout[0] + ((size_t)((bL + 2) * NN + v)) * NH + f0);
        float4 h1L = *(const float4*)(g_hout[1] + ((size_t)(bL * NN + v)) * NH + f0);
        float4 h1H = *(const float4*)(g_hout[1] + ((size_t)((bL + 2) * NN + v)) * NH + f0);
        float pL = oL.x * w2.x + oL.y * w2.y + oL.z * w2.z + oL.w * w2.w
                 + h0L.x * w0.x + h0L.y * w0.y + h0L.z * w0.z + h0L.w * w0.w
                 + h1L.x * w1.x + h1L.y * w1.y + h1L.z * w1.z + h1L.w * w1.w;
        float pH = oH.x * w2.x + oH.y * w2.y + oH.z * w2.z + oH.w * w2.w
                 + h0H.x * w0.x + h0H.y * w0.y + h0H.z * w0.z + h0H.w * w0.w
                 + h1H.x * w1.x + h1H.y * w1.y + h1H.z * w1.z + h1H.w * w1.w;
#pragma unroll
        for (int o = 8; o; o >>= 1) {        // reduce within 16-lane group
            pL += __shfl_xor_sync(0xffffffffu, pL, o);
            pH += __shfl_xor_sync(0xffffffffu, pH, o);
        }
        if ((lane & 15) == 0) {
            float fb = fcb[0];
            g_scores[bL * NN + v] = pL + fb;
            g_scores[(bL + 2) * NN + v] = pH + fb;
        }
    }
}

// ---------------------------------------------------------------------------
// h1[b,f] = sum_n scores[b,n] * lin1_w[n,f]
// ---------------------------------------------------------------------------
__global__ void lin1_kernel(const float* __restrict__ w) {
    int f = threadIdx.x;
    int chunk = (NN + gridDim.x - 1) / gridDim.x;
    int n0 = blockIdx.x * chunk;
    int n1 = n0 + chunk;
    if (n1 > NN) n1 = NN;

    float acc[NB] = {0.f, 0.f, 0.f, 0.f};
    for (int n = n0; n < n1; ++n) {
        float wv = w[(size_t)n * NFC + f];
#pragma unroll
        for (int b = 0; b < NB; ++b)
            acc[b] = fmaf(g_scores[b * NN + n], wv, acc[b]);
    }
#pragma unroll
    for (int b = 0; b < NB; ++b)
        atomicAdd(&g_h1[b * NFC + f], acc[b]);
}

__global__ void final_kernel(const float* __restrict__ l1b,
                             const float* __restrict__ l2w,
                             const float* __restrict__ l2b,
                             float* __restrict__ out) {
    __shared__ float s0[NFC], s1[NFC];
    int f = threadIdx.x;
    for (int b = 0; b < NB; ++b) {
        float hv = fmaxf(g_h1[b * NFC + f] + l1b[f], 0.f);
        s0[f] = hv * l2w[f * 2 + 0];
        s1[f] = hv * l2w[f * 2 + 1];
        __syncthreads();
        for (int off = 128; off; off >>= 1) {
            if (f < off) { s0[f] += s0[f + off]; s1[f] += s1[f + off]; }
            __syncthreads();
        }
        if (f == 0) {
            float l0 = s0[0] + l2b[0];
            float l1 = s1[0] + l2b[1];
            float m = fmaxf(l0, l1);
            float lse = m + logf(expf(l0 - m) + expf(l1 - m));
            out[b * 2 + 0] = l0 - lse;
            out[b * 2 + 1] = l1 - lse;
        }
        __syncthreads();
    }
}

// ---------------------------------------------------------------------------
// Launch
// ---------------------------------------------------------------------------
extern "C" void kernel_launch(void* const* d_in, const int* in_sizes, int n_in,
                              void* d_out, int out_size) {
    const float* x      = (const float*)d_in[0];
    const int*   ei     = (const int*)d_in[1];
    const float* W[3]   = {(const float*)d_in[3], (const float*)d_in[7],  (const float*)d_in[11]};
    const float* as_[3] = {(const float*)d_in[4], (const float*)d_in[8],  (const float*)d_in[12]};
    const float* ad_[3] = {(const float*)d_in[5], (const float*)d_in[9],  (const float*)d_in[13]};
    const float* bb[3]  = {(const float*)d_in[6], (const float*)d_in[10], (const float*)d_in[14]};
    const float* fcw    = (const float*)d_in[15];
    const float* fcb    = (const float*)d_in[16];
    const float* l1w    = (const float*)d_in[17];
    const float* l1b    = (const float*)d_in[18];
    const float* l2w    = (const float*)d_in[19];
    const float* l2b    = (const float*)d_in[20];
    float* out = (float*)d_out;

    zero_kernel<<<(NN + 255) / 256, 256>>>();
    hist_kernel<<<(NE + 255) / 256, 256>>>(ei);
    scan_kernel<<<1, 1024>>>();
    scatter_kernel<<<(NE + 255) / 256, 256>>>(ei);

    int gridT = (NB * NN + 7) / 8;
    int gridA = (NN + 7) / 8;

    transform_kernel<FIN0><<<gridT, 256>>>(x, W[0], as_[0], ad_[0], 0);
    agg_kernel<false><<<gridA, 256>>>(bb[0], 0, fcw, fcb);
    transform_kernel<NH><<<gridT, 256>>>(x, W[1], as_[1], ad_[1], 1);
    agg_kernel<false><<<gridA, 256>>>(bb[1], 1, fcw, fcb);
    transform_kernel<NH><<<gridT, 256>>>(x, W[2], as_[2], ad_[2], 2);
    agg_kernel<true><<<gridA, 256>>>(bb[2], 2, fcw, fcb);

    lin1_kernel<<<128, 256>>>(l1w);
    final_kernel<<<1, 256>>>(l1b, l2w, l2b, out);
}

// round 3
// speedup vs baseline: 1.2728x; 1.0352x over previous
#include <cuda_runtime.h>
#include <cuda_bf16.h>
#include <math.h>

#define NB 4
#define NN 15135
#define NE 302700
#define FIN0 8
#define NH 64
#define NFC 256
#define NEG_SLOPE 0.2f

// ---------------------------------------------------------------------------
// Static device scratch
// ---------------------------------------------------------------------------
__device__ int    g_deg[NN];
__device__ int    g_cur[NN];
__device__ int    g_rowptr[NN + 1];
__device__ int    g_col[NE];

__device__ float  g_hin[(size_t)NN * 256];       // [n][b*64+f] interleaved
__device__ float  g_hout[3][NB * NN * NH];       // [l][b][n][64]
__device__ float4 g_es4[NN];
__device__ float4 g_ed4[NN];
__device__ float4 g_w[NE];                       // unnormalized numerators
__device__ float  g_scores[NB * NN];
__device__ float  g_h1[NB * NFC];

__device__ __forceinline__ float lrelu(float x) { return x >= 0.f ? x : NEG_SLOPE * x; }

// ---------------------------------------------------------------------------
// CSR construction
// ---------------------------------------------------------------------------
__global__ void zero_kernel() {
    int i = blockIdx.x * blockDim.x + threadIdx.x;
    if (i < NN) g_deg[i] = 0;
    if (i < NB * NFC) g_h1[i] = 0.f;
}

__global__ void hist_kernel(const int* __restrict__ ei) {
    int e = blockIdx.x * blockDim.x + threadIdx.x;
    if (e < NE) atomicAdd(&g_deg[ei[NE + e]], 1);
}

// single-block scan, 4 elements per thread (4 tiles of 4096)
__global__ void scan_kernel() {
    __shared__ int warpsums[32];
    __shared__ int carry;
    int t = threadIdx.x, lane = t & 31, w = t >> 5;
    if (t == 0) { carry = 0; g_rowptr[0] = 0; }
    __syncthreads();
    for (int base = 0; base < NN; base += 4096) {
        int idx = base + t * 4;
        int v0 = (idx     < NN) ? g_deg[idx]     : 0;
        int v1 = (idx + 1 < NN) ? g_deg[idx + 1] : 0;
        int v2 = (idx + 2 < NN) ? g_deg[idx + 2] : 0;
        int v3 = (idx + 3 < NN) ? g_deg[idx + 3] : 0;
        int s0 = v0, s1 = s0 + v1, s2 = s1 + v2, s3 = s2 + v3;
        int x = s3;
#pragma unroll
        for (int off = 1; off < 32; off <<= 1) {
            int y = __shfl_up_sync(0xffffffffu, x, off);
            if (lane >= off) x += y;
        }
        if (lane == 31) warpsums[w] = x;
        __syncthreads();
        if (t < 32) {
            int s = warpsums[t];
#pragma unroll
            for (int off = 1; off < 32; off <<= 1) {
                int y = __shfl_up_sync(0xffffffffu, s, off);
                if (t >= off) s += y;
            }
            warpsums[t] = s;
        }
        __syncthreads();
        int pre = x - s3 + (w > 0 ? warpsums[w - 1] : 0) + carry;  // exclusive
        if (idx     < NN) { g_cur[idx]     = pre;           g_rowptr[idx + 1] = pre + s0; }
        if (idx + 1 < NN) { g_cur[idx + 1] = pre + s0;      g_rowptr[idx + 2] = pre + s1; }
        if (idx + 2 < NN) { g_cur[idx + 2] = pre + s1;      g_rowptr[idx + 3] = pre + s2; }
        if (idx + 3 < NN) { g_cur[idx + 3] = pre + s2;      g_rowptr[idx + 4] = pre + s3; }
        __syncthreads();
        if (t == 0) carry += warpsums[31];
        __syncthreads();
    }
}

__global__ void scatter_kernel(const int* __restrict__ ei) {
    int e = blockIdx.x * blockDim.x + threadIdx.x;
    if (e < NE) {
        int s = __ldg(ei + e);
        int d = __ldg(ei + NE + e);
        int pos = atomicAdd(&g_cur[d], 1);
        g_col[pos] = s;
    }
}

// ---------------------------------------------------------------------------
// Feature transform. One warp per (b,n). Coalesced row load + shfl broadcast.
// Each lane computes 2 consecutive features (float2 smem weight loads).
// ---------------------------------------------------------------------------
template <int FIN>
__global__ void transform_kernel(const float* __restrict__ x0,
                                 const float* __restrict__ W,
                                 const float* __restrict__ a_src,
                                 const float* __restrict__ a_dst,
                                 int layer) {
    __shared__ float Ws[FIN * NH];
    __shared__ float As[NH], Ad[NH];
    int t = threadIdx.x;
    for (int i = t; i < FIN * NH; i += blockDim.x) Ws[i] = W[i];
    if (t < NH) { As[t] = a_src[t]; Ad[t] = a_dst[t]; }
    __syncthreads();

    int warp = (blockIdx.x * blockDim.x + t) >> 5;
    int lane = t & 31;
    if (warp >= NB * NN) return;
    int b = warp / NN;
    int n = warp - b * NN;

    const float* in = (layer == 0) ? x0 : g_hout[layer - 1];
    const float* row = in + (size_t)warp * FIN;

    float xa = 0.f, xb = 0.f;
    if (FIN == 8) {
        if (lane < 8) xa = row[lane];
    } else {
        xa = row[lane];
        xb = row[lane + 32];
    }

    float2 acc = make_float2(0.f, 0.f);
#pragma unroll
    for (int f = 0; f < FIN; ++f) {
        float xf = __shfl_sync(0xffffffffu, (f < 32) ? xa : xb, f & 31);
        float2 w2 = *(const float2*)&Ws[f * NH + 2 * lane];
        acc.x = fmaf(xf, w2.x, acc.x);
        acc.y = fmaf(xf, w2.y, acc.y);
    }
    *(float2*)(g_hin + (size_t)n * 256 + b * 64 + 2 * lane) = acc;

    float e_s = acc.x * As[2 * lane] + acc.y * As[2 * lane + 1];
    float e_d = acc.x * Ad[2 * lane] + acc.y * Ad[2 * lane + 1];
#pragma unroll
    for (int o = 16; o; o >>= 1) {
        e_s += __shfl_xor_sync(0xffffffffu, e_s, o);
        e_d += __shfl_xor_sync(0xffffffffu, e_d, o);
    }
    if (lane == 0) {
        ((float*)g_es4)[n * 4 + b] = e_s;
        ((float*)g_ed4)[n * 4 + b] = e_d;
    }
}

// ---------------------------------------------------------------------------
// GAT aggregation: TWO warps per dst node, each self-contained for 2 batches.
//   half=0 -> batches 0,1 ; half=1 -> batches 2,3
// Within a warp: lanes 0-15 = batch lo features 4*(lane&15).., lanes 16-31 =
// batch hi. Per edge per warp: one float4 load + 4 FMA.
// ---------------------------------------------------------------------------
template <bool FUSE_SCORES>
__global__ void agg_kernel(const float* __restrict__ bias, int layer,
                           const float* __restrict__ fcw,
                           const float* __restrict__ fcb) {
    int gwarp = (blockIdx.x * blockDim.x + threadIdx.x) >> 5;
    int lane = threadIdx.x & 31;
    if (gwarp >= 2 * NN) return;
    int v = gwarp >> 1;
    int half = gwarp & 1;
    int r0 = g_rowptr[v];
    int r1 = g_rowptr[v + 1];

    const float2* es2p = (const float2*)g_es4;
    float2 ed2 = ((const float2*)g_ed4)[2 * v + half];
    float2 es2 = es2p[2 * v + half];
    float2 vself = make_float2(lrelu(es2.x + ed2.x), lrelu(es2.y + ed2.y));

    // ---- pass 1: max (cache first-edge logit per lane) ----
    int i0 = r0 + lane;
    bool have0 = (i0 < r1);
    float2 v0 = make_float2(0.f, 0.f);
    if (have0) {
        float2 e = es2p[2 * g_col[i0] + half];
        v0 = make_float2(lrelu(e.x + ed2.x), lrelu(e.y + ed2.y));
    }
    float2 mx = vself;
    if (have0) { mx.x = fmaxf(mx.x, v0.x); mx.y = fmaxf(mx.y, v0.y); }
    for (int i = i0 + 32; i < r1; i += 32) {
        float2 e = es2p[2 * g_col[i] + half];
        mx.x = fmaxf(mx.x, lrelu(e.x + ed2.x));
        mx.y = fmaxf(mx.y, lrelu(e.y + ed2.y));
    }
#pragma unroll
    for (int o = 16; o; o >>= 1) {
        mx.x = fmaxf(mx.x, __shfl_xor_sync(0xffffffffu, mx.x, o));
        mx.y = fmaxf(mx.y, __shfl_xor_sync(0xffffffffu, mx.y, o));
    }

    // ---- pass 2: exp, store numerators, sum ----
    float2 sm = make_float2(0.f, 0.f);
    float2 wself = make_float2(__expf(vself.x - mx.x), __expf(vself.y - mx.y));
    if (lane == 0) sm = wself;
    if (have0) {
        float2 ex = make_float2(__expf(v0.x - mx.x), __expf(v0.y - mx.y));
        ((float2*)&g_w[i0])[half] = ex;
        sm.x += ex.x; sm.y += ex.y;
    }
    for (int i = i0 + 32; i < r1; i += 32) {
        float2 e = es2p[2 * g_col[i] + half];
        float2 ex = make_float2(__expf(lrelu(e.x + ed2.x) - mx.x),
                                __expf(lrelu(e.y + ed2.y) - mx.y));
        ((float2*)&g_w[i])[half] = ex;
        sm.x += ex.x; sm.y += ex.y;
    }
#pragma unroll
    for (int o = 16; o; o >>= 1) {
        sm.x += __shfl_xor_sync(0xffffffffu, sm.x, o);
        sm.y += __shfl_xor_sync(0xffffffffu, sm.y, o);
    }
    bool loA = (lane < 16);
    float inv = 1.f / (loA ? sm.x : sm.y);

    // ---- pass 3: weighted gather ----
    int bidx = 2 * half + (lane >> 4);       // batch this lane serves
    int f0 = (lane & 15) * 4;
    int off = bidx * 64 + f0;                // offset within g_hin row

    float4 acc = make_float4(0.f, 0.f, 0.f, 0.f);
    int i = r0;
    for (; i + 2 <= r1; i += 2) {
        int sA = g_col[i];
        int sB = g_col[i + 1];
        float2 wA = ((const float2*)&g_w[i])[half];
        float2 wB = ((const float2*)&g_w[i + 1])[half];
        float4 hA = *(const float4*)(g_hin + (size_t)sA * 256 + off);
        float4 hB = *(const float4*)(g_hin + (size_t)sB * 256 + off);
        float wa = (loA ? wA.x : wA.y) * inv;
        float wb = (loA ? wB.x : wB.y) * inv;
        acc.x = fmaf(wa, hA.x, acc.x); acc.y = fmaf(wa, hA.y, acc.y);
        acc.z = fmaf(wa, hA.z, acc.z); acc.w = fmaf(wa, hA.w, acc.w);
        acc.x = fmaf(wb, hB.x, acc.x); acc.y = fmaf(wb, hB.y, acc.y);
        acc.z = fmaf(wb, hB.z, acc.z); acc.w = fmaf(wb, hB.w, acc.w);
    }
    if (i < r1) {
        int s = g_col[i];
        float2 w2 = ((const float2*)&g_w[i])[half];
        float4 h = *(const float4*)(g_hin + (size_t)s * 256 + off);
        float wn = (loA ? w2.x : w2.y) * inv;
        acc.x = fmaf(wn, h.x, acc.x); acc.y = fmaf(wn, h.y, acc.y);
        acc.z = fmaf(wn, h.z, acc.z); acc.w = fmaf(wn, h.w, acc.w);
    }
    {   // self loop
        float wn = (loA ? wself.x : wself.y) * inv;
        float4 h = *(const float4*)(g_hin + (size_t)v * 256 + off);
        acc.x = fmaf(wn, h.x, acc.x); acc.y = fmaf(wn, h.y, acc.y);
        acc.z = fmaf(wn, h.z, acc.z); acc.w = fmaf(wn, h.w, acc.w);
    }

    float4 b4 = *(const float4*)(bias + f0);
    float4 o4;
    o4.x = fmaxf(acc.x + b4.x, 0.f); o4.y = fmaxf(acc.y + b4.y, 0.f);
    o4.z = fmaxf(acc.z + b4.z, 0.f); o4.w = fmaxf(acc.w + b4.w, 0.f);
    *(float4*)(g_hout[layer] + ((size_t)(bidx * NN + v)) * NH + f0) = o4;

    if (FUSE_SCORES) {
        float4 w0 = make_float4(fcw[(f0 + 0) * 3 + 0], fcw[(f0 + 1) * 3 + 0],
                                fcw[(f0 + 2) * 3 + 0], fcw[(f0 + 3) * 3 + 0]);
        float4 w1 = make_float4(fcw[(f0 + 0) * 3 + 1], fcw[(f0 + 1) * 3 + 1],
                                fcw[(f0 + 2) * 3 + 1], fcw[(f0 + 3) * 3 + 1]);
        float4 w2 = make_float4(fcw[(f0 + 0) * 3 + 2], fcw[(f0 + 1) * 3 + 2],
                                fcw[(f0 + 2) * 3 + 2], fcw[(f0 + 3) * 3 + 2]);
        float4 h0 = *(const float4*)(g_hout[0] + ((size_t)(bidx * NN + v)) * NH + f0);
        float4 h1 = *(const float4*)(g_hout[1] + ((size_t)(bidx * NN + v)) * NH + f0);
        float p = o4.x * w2.x + o4.y * w2.y + o4.z * w2.z + o4.w * w2.w
                + h0.x * w0.x + h0.y * w0.y + h0.z * w0.z + h0.w * w0.w
                + h1.x * w1.x + h1.y * w1.y + h1.z * w1.z + h1.w * w1.w;
#pragma unroll
        for (int o = 8; o; o >>= 1) p += __shfl_xor_sync(0xffffffffu, p, o);
        if ((lane & 15) == 0) g_scores[bidx * NN + v] = p + fcb[0];
    }
}

// ---------------------------------------------------------------------------
// h1[b,f] = sum_n scores[b,n] * lin1_w[n,f]
// ---------------------------------------------------------------------------
__global__ void lin1_kernel(const float* __restrict__ w) {
    int f = threadIdx.x;
    int chunk = (NN + gridDim.x - 1) / gridDim.x;
    int n0 = blockIdx.x * chunk;
    int n1 = n0 + chunk;
    if (n1 > NN) n1 = NN;

    float acc[NB] = {0.f, 0.f, 0.f, 0.f};
    for (int n = n0; n < n1; ++n) {
        float wv = w[(size_t)n * NFC + f];
#pragma unroll
        for (int b = 0; b < NB; ++b)
            acc[b] = fmaf(g_scores[b * NN + n], wv, acc[b]);
    }
#pragma unroll
    for (int b = 0; b < NB; ++b)
        atomicAdd(&g_h1[b * NFC + f], acc[b]);
}

__global__ void final_kernel(const float* __restrict__ l1b,
                             const float* __restrict__ l2w,
                             const float* __restrict__ l2b,
                             float* __restrict__ out) {
    __shared__ float s0[NFC], s1[NFC];
    int f = threadIdx.x;
    for (int b = 0; b < NB; ++b) {
        float hv = fmaxf(g_h1[b * NFC + f] + l1b[f], 0.f);
        s0[f] = hv * l2w[f * 2 + 0];
        s1[f] = hv * l2w[f * 2 + 1];
        __syncthreads();
        for (int off = 128; off; off >>= 1) {
            if (f < off) { s0[f] += s0[f + off]; s1[f] += s1[f + off]; }
            __syncthreads();
        }
        if (f == 0) {
            float l0 = s0[0] + l2b[0];
            float l1 = s1[0] + l2b[1];
            float m = fmaxf(l0, l1);
            float lse = m + logf(expf(l0 - m) + expf(l1 - m));
            out[b * 2 + 0] = l0 - lse;
            out[b * 2 + 1] = l1 - lse;
        }
        __syncthreads();
    }
}

// ---------------------------------------------------------------------------
// Launch
// ---------------------------------------------------------------------------
extern "C" void kernel_launch(void* const* d_in, const int* in_sizes, int n_in,
                              void* d_out, int out_size) {
    const float* x      = (const float*)d_in[0];
    const int*   ei     = (const int*)d_in[1];
    const float* W[3]   = {(const float*)d_in[3], (const float*)d_in[7],  (const float*)d_in[11]};
    const float* as_[3] = {(const float*)d_in[4], (const float*)d_in[8],  (const float*)d_in[12]};
    const float* ad_[3] = {(const float*)d_in[5], (const float*)d_in[9],  (const float*)d_in[13]};
    const float* bb[3]  = {(const float*)d_in[6], (const float*)d_in[10], (const float*)d_in[14]};
    const float* fcw    = (const float*)d_in[15];
    const float* fcb    = (const float*)d_in[16];
    const float* l1w    = (const float*)d_in[17];
    const float* l1b    = (const float*)d_in[18];
    const float* l2w    = (const float*)d_in[19];
    const float* l2b    = (const float*)d_in[20];
    float* out = (float*)d_out;

    zero_kernel<<<(NN + 255) / 256, 256>>>();
    hist_kernel<<<(NE + 255) / 256, 256>>>(ei);
    scan_kernel<<<1, 1024>>>();
    scatter_kernel<<<(NE + 255) / 256, 256>>>(ei);

    int gridT = (NB * NN + 7) / 8;
    int gridA = (2 * NN + 7) / 8;    // two warps per node

    transform_kernel<FIN0><<<gridT, 256>>>(x, W[0], as_[0], ad_[0], 0);
    agg_kernel<false><<<gridA, 256>>>(bb[0], 0, fcw, fcb);
    transform_kernel<NH><<<gridT, 256>>>(x, W[1], as_[1], ad_[1], 1);
    agg_kernel<false><<<gridA, 256>>>(bb[1], 1, fcw, fcb);
    transform_kernel<NH><<<gridT, 256>>>(x, W[2], as_[2], ad_[2], 2);
    agg_kernel<true><<<gridA, 256>>>(bb[2], 2, fcw, fcb);

    lin1_kernel<<<128, 256>>>(l1w);
    final_kernel<<<1, 256>>>(l1b, l2w, l2b, out);
}